// round 2
// baseline (speedup 1.0000x reference)
#include <cuda_runtime.h>

// CommNet fused kernel: one CTA per batch element (grid = 1024).
// h, h0, A tiles (64 x 256 fp32) persist in SMEM across all 4 comm steps.
// x@W1 rewritten as h@(W1a - inv*W1b) + h0@W1c + bcast(inv * S@W1b).

#define HID   256
#define MAG   64
#define PAD   260          // row pitch (floats) for 64-row SMEM tiles; mult of 4
#define KT    16           // K-tile for weight streaming
#define STEPS 4
#define INVF  (1.0f/63.0f)

__global__ void __launch_bounds__(256, 1) commnet_kernel(
    const int*   __restrict__ ids,   // (B, 64)
    const float* __restrict__ W1,    // (768, 256) row-major
    const float* __restrict__ b1,    // (256)
    const float* __restrict__ W2,    // (256, 256)
    const float* __restrict__ b2,    // (256)
    const float* __restrict__ Wd,    // (256, 16)
    const float* __restrict__ bd,    // (16)
    const float* __restrict__ emb,   // (1000, 256)
    float*       __restrict__ out)   // (B, 64, 16)
{
    extern __shared__ float smem[];
    float* hS  = smem;                  // [64][PAD]
    float* h0S = hS  + MAG * PAD;       // [64][PAD]
    float* aS  = h0S + MAG * PAD;       // [64][PAD]
    float* bS  = aS  + MAG * PAD;       // [KT][256]
    float* Sv  = bS  + KT * HID;        // [256]
    float* Tv  = Sv  + HID;             // [256]

    const int b   = blockIdx.x;
    const int tid = threadIdx.x;
    const int ty  = tid >> 5;           // 0..7  : row group (8 rows)
    const int tx  = tid & 31;           // 0..31 : col group (8 cols)

    const int* myids = ids + b * MAG;

    // ---- gather embeddings into h and h0 ----
    for (int i = tid; i < MAG * (HID / 4); i += 256) {
        int row = i >> 6;               // 0..63
        int c4  = i & 63;               // 0..63 (float4 index)
        int aid = myids[row];
        float4 v = reinterpret_cast<const float4*>(emb + aid * HID)[c4];
        reinterpret_cast<float4*>(hS  + row * PAD)[c4] = v;
        reinterpret_cast<float4*>(h0S + row * PAD)[c4] = v;
    }

    const int brow = tid >> 4;          // 0..15 : Bsm row this thread loads
    const int bcol = (tid & 15) << 4;   // 0..240: Bsm col start (16 floats)

    for (int step = 0; step < STEPS; ++step) {
        __syncthreads();

        // ---- S[c] = sum_j h[j][c] ----
        {
            float s = 0.f;
            #pragma unroll 8
            for (int j = 0; j < MAG; ++j) s += hS[j * PAD + tid];
            Sv[tid] = s;
        }
        __syncthreads();

        // ---- Tv[c] = b1[c] + inv * (S @ W1b)[c], W1b = W1 rows 256..511 ----
        {
            const float* w = W1 + HID * HID + tid;
            float acc = 0.f;
            #pragma unroll 8
            for (int k = 0; k < HID; ++k) acc = fmaf(Sv[k], w[k * HID], acc);
            Tv[tid] = fmaf(acc, INVF, b1[tid]);
        }
        // (visibility of Tv covered by the first tile __syncthreads below)

        // ================= GEMM1: A = relu(h@W1eff + h0@W1c + Tv) ========
        float acc[8][8];
        #pragma unroll
        for (int i = 0; i < 8; ++i)
            #pragma unroll
            for (int j = 0; j < 8; ++j) acc[i][j] = 0.f;

        // pass A: h @ (W1a - inv*W1b)
        for (int k0 = 0; k0 < HID; k0 += KT) {
            __syncthreads();
            {
                const float4* g1 = reinterpret_cast<const float4*>(W1 + (k0 + brow) * HID + bcol);
                const float4* g2 = reinterpret_cast<const float4*>(W1 + (HID + k0 + brow) * HID + bcol);
                float4* dst = reinterpret_cast<float4*>(bS + brow * HID + bcol);
                #pragma unroll
                for (int q = 0; q < 4; ++q) {
                    float4 x = g1[q], y = g2[q];
                    dst[q] = make_float4(fmaf(-INVF, y.x, x.x), fmaf(-INVF, y.y, x.y),
                                         fmaf(-INVF, y.z, x.z), fmaf(-INVF, y.w, x.w));
                }
            }
            __syncthreads();
            #pragma unroll
            for (int kk = 0; kk < KT; ++kk) {
                float af[8];
                #pragma unroll
                for (int i = 0; i < 8; ++i) af[i] = hS[(ty * 8 + i) * PAD + k0 + kk];
                float4 p0 = reinterpret_cast<const float4*>(bS + kk * HID + tx * 8)[0];
                float4 p1 = reinterpret_cast<const float4*>(bS + kk * HID + tx * 8)[1];
                float bf[8] = {p0.x, p0.y, p0.z, p0.w, p1.x, p1.y, p1.z, p1.w};
                #pragma unroll
                for (int i = 0; i < 8; ++i)
                    #pragma unroll
                    for (int j = 0; j < 8; ++j) acc[i][j] = fmaf(af[i], bf[j], acc[i][j]);
            }
        }
        // pass B: h0 @ W1c (rows 512..767)
        for (int k0 = 0; k0 < HID; k0 += KT) {
            __syncthreads();
            {
                const float4* g = reinterpret_cast<const float4*>(W1 + (2 * HID + k0 + brow) * HID + bcol);
                float4* dst = reinterpret_cast<float4*>(bS + brow * HID + bcol);
                #pragma unroll
                for (int q = 0; q < 4; ++q) dst[q] = g[q];
            }
            __syncthreads();
            #pragma unroll
            for (int kk = 0; kk < KT; ++kk) {
                float af[8];
                #pragma unroll
                for (int i = 0; i < 8; ++i) af[i] = h0S[(ty * 8 + i) * PAD + k0 + kk];
                float4 p0 = reinterpret_cast<const float4*>(bS + kk * HID + tx * 8)[0];
                float4 p1 = reinterpret_cast<const float4*>(bS + kk * HID + tx * 8)[1];
                float bf[8] = {p0.x, p0.y, p0.z, p0.w, p1.x, p1.y, p1.z, p1.w};
                #pragma unroll
                for (int i = 0; i < 8; ++i)
                    #pragma unroll
                    for (int j = 0; j < 8; ++j) acc[i][j] = fmaf(af[i], bf[j], acc[i][j]);
            }
        }
        // epilogue1: aS = relu(acc + Tv)
        #pragma unroll
        for (int i = 0; i < 8; ++i)
            #pragma unroll
            for (int j = 0; j < 8; ++j) {
                float v = acc[i][j] + Tv[tx * 8 + j];
                aS[(ty * 8 + i) * PAD + tx * 8 + j] = v > 0.f ? v : 0.f;
            }

        // ================= GEMM2: h += aS @ W2 + b2 ======================
        #pragma unroll
        for (int i = 0; i < 8; ++i)
            #pragma unroll
            for (int j = 0; j < 8; ++j) acc[i][j] = 0.f;

        for (int k0 = 0; k0 < HID; k0 += KT) {
            __syncthreads();   // also makes aS writes visible on first iter
            {
                const float4* g = reinterpret_cast<const float4*>(W2 + (k0 + brow) * HID + bcol);
                float4* dst = reinterpret_cast<float4*>(bS + brow * HID + bcol);
                #pragma unroll
                for (int q = 0; q < 4; ++q) dst[q] = g[q];
            }
            __syncthreads();
            #pragma unroll
            for (int kk = 0; kk < KT; ++kk) {
                float af[8];
                #pragma unroll
                for (int i = 0; i < 8; ++i) af[i] = aS[(ty * 8 + i) * PAD + k0 + kk];
                float4 p0 = reinterpret_cast<const float4*>(bS + kk * HID + tx * 8)[0];
                float4 p1 = reinterpret_cast<const float4*>(bS + kk * HID + tx * 8)[1];
                float bf[8] = {p0.x, p0.y, p0.z, p0.w, p1.x, p1.y, p1.z, p1.w};
                #pragma unroll
                for (int i = 0; i < 8; ++i)
                    #pragma unroll
                    for (int j = 0; j < 8; ++j) acc[i][j] = fmaf(af[i], bf[j], acc[i][j]);
            }
        }
        // epilogue2: residual update (each h element owned by exactly one thread)
        #pragma unroll
        for (int i = 0; i < 8; ++i)
            #pragma unroll
            for (int j = 0; j < 8; ++j)
                hS[(ty * 8 + i) * PAD + tx * 8 + j] += acc[i][j] + b2[tx * 8 + j];
    }

    __syncthreads();
    // ---- logits: out[b][j][:] = h[j] @ Wd + bd ----
    {
        int j  = tid >> 2;              // agent row 0..63
        int q4 = tid & 3;               // which 4 actions
        float4 o = reinterpret_cast<const float4*>(bd)[q4];
        float ox = o.x, oy = o.y, oz = o.z, ow = o.w;
        #pragma unroll 8
        for (int k = 0; k < HID; ++k) {
            float hv = hS[j * PAD + k];
            float4 w = reinterpret_cast<const float4*>(Wd + k * 16)[q4];
            ox = fmaf(hv, w.x, ox); oy = fmaf(hv, w.y, oy);
            oz = fmaf(hv, w.z, oz); ow = fmaf(hv, w.w, ow);
        }
        reinterpret_cast<float4*>(out + (b * MAG + j) * 16)[q4] = make_float4(ox, oy, oz, ow);
    }
}

extern "C" void kernel_launch(void* const* d_in, const int* in_sizes, int n_in,
                              void* d_out, int out_size)
{
    // metadata order: agent_ids, emb, W1, b1, W2, b2, Wd, bd
    const int*   ids = (const int*)  d_in[0];
    const float* emb = (const float*)d_in[1];
    const float* W1  = (const float*)d_in[2];
    const float* b1  = (const float*)d_in[3];
    const float* W2  = (const float*)d_in[4];
    const float* b2  = (const float*)d_in[5];
    const float* Wd  = (const float*)d_in[6];
    const float* bd  = (const float*)d_in[7];
    float* out = (float*)d_out;

    const int B = in_sizes[0] / MAG;   // 1024

    const int smem_bytes = (3 * MAG * PAD + KT * HID + 2 * HID) * (int)sizeof(float);
    cudaFuncSetAttribute(commnet_kernel,
                         cudaFuncAttributeMaxDynamicSharedMemorySize, smem_bytes);

    commnet_kernel<<<B, 256, smem_bytes>>>(ids, W1, b1, W2, b2, Wd, bd, emb, out);
}

// round 3
// speedup vs baseline: 1.0095x; 1.0095x over previous
#include <cuda_runtime.h>

// CommNet fused kernel: one CTA per batch element (grid = 1024).
// h, h0, A tiles (64 x 256 fp32) persist in SMEM across all 4 comm steps.
// x@W1 rewritten as h@(W1a - inv*W1b) + h0@W1c + bcast(inv * S@W1b).

#define HID   256
#define MAG   64
#define PAD   260          // row pitch (floats) for 64-row SMEM tiles; mult of 4
#define KT    16           // K-tile for weight streaming
#define STEPS 4
#define INVF  (1.0f/63.0f)

__global__ void __launch_bounds__(256, 1) commnet_kernel(
    const int*   __restrict__ ids,   // (B, 64)
    const float* __restrict__ W1,    // (768, 256) row-major
    const float* __restrict__ b1,    // (256)
    const float* __restrict__ W2,    // (256, 256)
    const float* __restrict__ b2,    // (256)
    const float* __restrict__ Wd,    // (256, 16)
    const float* __restrict__ bd,    // (16)
    const float* __restrict__ emb,   // (1000, 256)
    float*       __restrict__ out)   // (B, 64, 16)
{
    extern __shared__ float smem[];
    float* hS  = smem;                  // [64][PAD]
    float* h0S = hS  + MAG * PAD;       // [64][PAD]
    float* aS  = h0S + MAG * PAD;       // [64][PAD]
    float* bS  = aS  + MAG * PAD;       // [KT][256]
    float* Sv  = bS  + KT * HID;        // [256]
    float* Tv  = Sv  + HID;             // [256]

    const int b   = blockIdx.x;
    const int tid = threadIdx.x;
    const int ty  = tid >> 5;           // 0..7  : row group (8 rows)
    const int tx  = tid & 31;           // 0..31 : col group (8 cols)

    const int* myids = ids + b * MAG;

    // ---- gather embeddings into h and h0 ----
    for (int i = tid; i < MAG * (HID / 4); i += 256) {
        int row = i >> 6;               // 0..63
        int c4  = i & 63;               // 0..63 (float4 index)
        int aid = myids[row];
        float4 v = reinterpret_cast<const float4*>(emb + aid * HID)[c4];
        reinterpret_cast<float4*>(hS  + row * PAD)[c4] = v;
        reinterpret_cast<float4*>(h0S + row * PAD)[c4] = v;
    }

    const int brow = tid >> 4;          // 0..15 : Bsm row this thread loads
    const int bcol = (tid & 15) << 4;   // 0..240: Bsm col start (16 floats)

    for (int step = 0; step < STEPS; ++step) {
        __syncthreads();

        // ---- S[c] = sum_j h[j][c] ----
        {
            float s = 0.f;
            #pragma unroll 8
            for (int j = 0; j < MAG; ++j) s += hS[j * PAD + tid];
            Sv[tid] = s;
        }
        __syncthreads();

        // ---- Tv[c] = b1[c] + inv * (S @ W1b)[c], W1b = W1 rows 256..511 ----
        {
            const float* w = W1 + HID * HID + tid;
            float acc = 0.f;
            #pragma unroll 8
            for (int k = 0; k < HID; ++k) acc = fmaf(Sv[k], w[k * HID], acc);
            Tv[tid] = fmaf(acc, INVF, b1[tid]);
        }
        // (visibility of Tv covered by the first tile __syncthreads below)

        // ================= GEMM1: A = relu(h@W1eff + h0@W1c + Tv) ========
        float acc[8][8];
        #pragma unroll
        for (int i = 0; i < 8; ++i)
            #pragma unroll
            for (int j = 0; j < 8; ++j) acc[i][j] = 0.f;

        // pass A: h @ (W1a - inv*W1b)
        for (int k0 = 0; k0 < HID; k0 += KT) {
            __syncthreads();
            {
                const float4* g1 = reinterpret_cast<const float4*>(W1 + (k0 + brow) * HID + bcol);
                const float4* g2 = reinterpret_cast<const float4*>(W1 + (HID + k0 + brow) * HID + bcol);
                float4* dst = reinterpret_cast<float4*>(bS + brow * HID + bcol);
                #pragma unroll
                for (int q = 0; q < 4; ++q) {
                    float4 x = g1[q], y = g2[q];
                    dst[q] = make_float4(fmaf(-INVF, y.x, x.x), fmaf(-INVF, y.y, x.y),
                                         fmaf(-INVF, y.z, x.z), fmaf(-INVF, y.w, x.w));
                }
            }
            __syncthreads();
            #pragma unroll
            for (int kk = 0; kk < KT; ++kk) {
                float af[8];
                #pragma unroll
                for (int i = 0; i < 8; ++i) af[i] = hS[(ty * 8 + i) * PAD + k0 + kk];
                float4 p0 = reinterpret_cast<const float4*>(bS + kk * HID + tx * 8)[0];
                float4 p1 = reinterpret_cast<const float4*>(bS + kk * HID + tx * 8)[1];
                float bf[8] = {p0.x, p0.y, p0.z, p0.w, p1.x, p1.y, p1.z, p1.w};
                #pragma unroll
                for (int i = 0; i < 8; ++i)
                    #pragma unroll
                    for (int j = 0; j < 8; ++j) acc[i][j] = fmaf(af[i], bf[j], acc[i][j]);
            }
        }
        // pass B: h0 @ W1c (rows 512..767)
        for (int k0 = 0; k0 < HID; k0 += KT) {
            __syncthreads();
            {
                const float4* g = reinterpret_cast<const float4*>(W1 + (2 * HID + k0 + brow) * HID + bcol);
                float4* dst = reinterpret_cast<float4*>(bS + brow * HID + bcol);
                #pragma unroll
                for (int q = 0; q < 4; ++q) dst[q] = g[q];
            }
            __syncthreads();
            #pragma unroll
            for (int kk = 0; kk < KT; ++kk) {
                float af[8];
                #pragma unroll
                for (int i = 0; i < 8; ++i) af[i] = h0S[(ty * 8 + i) * PAD + k0 + kk];
                float4 p0 = reinterpret_cast<const float4*>(bS + kk * HID + tx * 8)[0];
                float4 p1 = reinterpret_cast<const float4*>(bS + kk * HID + tx * 8)[1];
                float bf[8] = {p0.x, p0.y, p0.z, p0.w, p1.x, p1.y, p1.z, p1.w};
                #pragma unroll
                for (int i = 0; i < 8; ++i)
                    #pragma unroll
                    for (int j = 0; j < 8; ++j) acc[i][j] = fmaf(af[i], bf[j], acc[i][j]);
            }
        }
        // epilogue1: aS = relu(acc + Tv)
        #pragma unroll
        for (int i = 0; i < 8; ++i)
            #pragma unroll
            for (int j = 0; j < 8; ++j) {
                float v = acc[i][j] + Tv[tx * 8 + j];
                aS[(ty * 8 + i) * PAD + tx * 8 + j] = v > 0.f ? v : 0.f;
            }

        // ================= GEMM2: h += aS @ W2 + b2 ======================
        #pragma unroll
        for (int i = 0; i < 8; ++i)
            #pragma unroll
            for (int j = 0; j < 8; ++j) acc[i][j] = 0.f;

        for (int k0 = 0; k0 < HID; k0 += KT) {
            __syncthreads();   // also makes aS writes visible on first iter
            {
                const float4* g = reinterpret_cast<const float4*>(W2 + (k0 + brow) * HID + bcol);
                float4* dst = reinterpret_cast<float4*>(bS + brow * HID + bcol);
                #pragma unroll
                for (int q = 0; q < 4; ++q) dst[q] = g[q];
            }
            __syncthreads();
            #pragma unroll
            for (int kk = 0; kk < KT; ++kk) {
                float af[8];
                #pragma unroll
                for (int i = 0; i < 8; ++i) af[i] = aS[(ty * 8 + i) * PAD + k0 + kk];
                float4 p0 = reinterpret_cast<const float4*>(bS + kk * HID + tx * 8)[0];
                float4 p1 = reinterpret_cast<const float4*>(bS + kk * HID + tx * 8)[1];
                float bf[8] = {p0.x, p0.y, p0.z, p0.w, p1.x, p1.y, p1.z, p1.w};
                #pragma unroll
                for (int i = 0; i < 8; ++i)
                    #pragma unroll
                    for (int j = 0; j < 8; ++j) acc[i][j] = fmaf(af[i], bf[j], acc[i][j]);
            }
        }
        // epilogue2: residual update (each h element owned by exactly one thread)
        #pragma unroll
        for (int i = 0; i < 8; ++i)
            #pragma unroll
            for (int j = 0; j < 8; ++j)
                hS[(ty * 8 + i) * PAD + tx * 8 + j] += acc[i][j] + b2[tx * 8 + j];
    }

    __syncthreads();
    // ---- logits: out[b][j][:] = h[j] @ Wd + bd ----
    {
        int j  = tid >> 2;              // agent row 0..63
        int q4 = tid & 3;               // which 4 actions
        float4 o = reinterpret_cast<const float4*>(bd)[q4];
        float ox = o.x, oy = o.y, oz = o.z, ow = o.w;
        #pragma unroll 8
        for (int k = 0; k < HID; ++k) {
            float hv = hS[j * PAD + k];
            float4 w = reinterpret_cast<const float4*>(Wd + k * 16)[q4];
            ox = fmaf(hv, w.x, ox); oy = fmaf(hv, w.y, oy);
            oz = fmaf(hv, w.z, oz); ow = fmaf(hv, w.w, ow);
        }
        reinterpret_cast<float4*>(out + (b * MAG + j) * 16)[q4] = make_float4(ox, oy, oz, ow);
    }
}

extern "C" void kernel_launch(void* const* d_in, const int* in_sizes, int n_in,
                              void* d_out, int out_size)
{
    // metadata order: agent_ids, emb, W1, b1, W2, b2, Wd, bd
    const int*   ids = (const int*)  d_in[0];
    const float* emb = (const float*)d_in[1];
    const float* W1  = (const float*)d_in[2];
    const float* b1  = (const float*)d_in[3];
    const float* W2  = (const float*)d_in[4];
    const float* b2  = (const float*)d_in[5];
    const float* Wd  = (const float*)d_in[6];
    const float* bd  = (const float*)d_in[7];
    float* out = (float*)d_out;

    const int B = in_sizes[0] / MAG;   // 1024

    const int smem_bytes = (3 * MAG * PAD + KT * HID + 2 * HID) * (int)sizeof(float);
    cudaFuncSetAttribute(commnet_kernel,
                         cudaFuncAttributeMaxDynamicSharedMemorySize, smem_bytes);

    commnet_kernel<<<B, 256, smem_bytes>>>(ids, W1, b1, W2, b2, Wd, bd, emb, out);
}

// round 5
// speedup vs baseline: 4.4321x; 4.3905x over previous
#include <cuda_runtime.h>
#include <cuda_bf16.h>
#include <cstdint>

// ============================================================================
// CommNet via warp-level tensor cores (mma.sync m16n8k16 bf16, compute_100-safe)
// 1 batch per CTA (M=64), 512 threads = 16 warps, warp w owns n in [16w,16w+16).
// h stored in SMEM as bf16 (hi,lo) split pairs in A-fragment layout S[kpair][m].
// D = Ahi*Bhi + Ahi*Blo + Alo*Bhi   (fp32 accumulators).
// ============================================================================

#define HID    256
#define MAG    64
#define STEPS  4
#define INVF   (1.0f/63.0f)
#define SPITCH 72              // b32 pitch of S[pair][*] (8t+g conflict-free)

// SMEM (bytes): sHi 36864 | sLo 36864 | G0 73728 | Sv 1024 | Tv 1024
#define SMEM_BYTES 149504

// ---------------- device scratch (prep-packed weights) ----------------
// gPk[g][ (s*32 + u)*32 + lane ] = {bh0, bh1, bl0, bl1} B-fragment pack
//   g: 0 = W1eff (W1a - inv*W1b), 1 = W1c, 2 = W2
__device__ uint4 gPk[3][16384];
__device__ float gW1bT[HID * HID];     // W1b transposed: [c][k]

// ---------------- helpers ----------------
__device__ __forceinline__ uint32_t pack_hi2(float x0, float x1,
                                             __nv_bfloat16& h0, __nv_bfloat16& h1) {
    h0 = __float2bfloat16(x0); h1 = __float2bfloat16(x1);
    __nv_bfloat162 p; p.x = h0; p.y = h1;
    return *reinterpret_cast<uint32_t*>(&p);
}
__device__ __forceinline__ void split2(float x0, float x1, uint32_t& hi, uint32_t& lo) {
    __nv_bfloat16 h0, h1;
    hi = pack_hi2(x0, x1, h0, h1);
    __nv_bfloat162 l;
    l.x = __float2bfloat16(x0 - __bfloat162float(h0));
    l.y = __float2bfloat16(x1 - __bfloat162float(h1));
    lo = *reinterpret_cast<uint32_t*>(&l);
}
__device__ __forceinline__ float2 unsplit(uint32_t hi, uint32_t lo) {
    __nv_bfloat162 h = *reinterpret_cast<__nv_bfloat162*>(&hi);
    __nv_bfloat162 l = *reinterpret_cast<__nv_bfloat162*>(&lo);
    return make_float2(__bfloat162float(h.x) + __bfloat162float(l.x),
                       __bfloat162float(h.y) + __bfloat162float(l.y));
}

#define MMA(c, a, B0, B1)                                                      \
    asm volatile("mma.sync.aligned.m16n8k16.row.col.f32.bf16.bf16.f32 "        \
                 "{%0,%1,%2,%3},{%4,%5,%6,%7},{%8,%9},{%0,%1,%2,%3};"          \
                 : "+f"((c)[0]), "+f"((c)[1]), "+f"((c)[2]), "+f"((c)[3])      \
                 : "r"((a)[0]), "r"((a)[1]), "r"((a)[2]), "r"((a)[3]),         \
                   "r"(B0), "r"(B1));

// ---------------- prep kernels ----------------
__global__ void prep_pack(const float* __restrict__ W1, const float* __restrict__ W2) {
    int idx = blockIdx.x * 256 + threadIdx.x;          // 3 * 16384
    int gm = idx >> 14;
    int r  = idx & 16383;
    int s  = r >> 10;
    int u  = (r >> 5) & 31;
    int l  = r & 31;
    int g  = l >> 2, t = l & 3;
    int n  = u * 8 + g;
    int kb = s * 16 + 2 * t;
    int ks[4] = { kb, kb + 1, kb + 8, kb + 9 };
    float v[4];
    #pragma unroll
    for (int q = 0; q < 4; ++q) {
        int k = ks[q];
        if (gm == 0)      v[q] = W1[k * HID + n] - INVF * W1[(HID + k) * HID + n];
        else if (gm == 1) v[q] = W1[(2 * HID + k) * HID + n];
        else              v[q] = W2[k * HID + n];
    }
    uint32_t bh0, bl0, bh1, bl1;
    split2(v[0], v[1], bh0, bl0);
    split2(v[2], v[3], bh1, bl1);
    gPk[gm][r] = make_uint4(bh0, bh1, bl0, bl1);
}
__global__ void prep_t(const float* __restrict__ W1) {
    int c = blockIdx.x, k = threadIdx.x;
    gW1bT[c * HID + k] = W1[(HID + k) * HID + c];
}

// ---------------- GEMM pass ----------------
__device__ __forceinline__ void gemm_pass(const uint4* __restrict__ bp,
                                          float (&acc)[4][2][4],
                                          const uint32_t* __restrict__ sHi,
                                          const uint32_t* __restrict__ sLo,
                                          int w, int lane, int g, int t) {
    const uint4* bq = bp + 2 * w * 32 + lane;
    uint4 bb = __ldg(bq);                               // s=0, j=0
    #pragma unroll 2
    for (int s = 0; s < 16; ++s) {
        uint32_t ah[4][4], al[4][4];
        int kp0 = (s * 8 + t) * SPITCH, kp2 = kp0 + 4 * SPITCH;
        #pragma unroll
        for (int mt = 0; mt < 4; ++mt) {
            int m0 = mt * 16 + g;
            ah[mt][0] = sHi[kp0 + m0]; ah[mt][1] = sHi[kp0 + m0 + 8];
            ah[mt][2] = sHi[kp2 + m0]; ah[mt][3] = sHi[kp2 + m0 + 8];
            al[mt][0] = sLo[kp0 + m0]; al[mt][1] = sLo[kp0 + m0 + 8];
            al[mt][2] = sLo[kp2 + m0]; al[mt][3] = sLo[kp2 + m0 + 8];
        }
        #pragma unroll
        for (int j = 0; j < 2; ++j) {
            int q  = s * 2 + j;
            int nq = q < 31 ? q + 1 : 31;               // prefetch next frag
            uint4 bbn = __ldg(bq + (nq >> 1) * 1024 + (nq & 1) * 32);
            #pragma unroll
            for (int mt = 0; mt < 4; ++mt) {
                MMA(acc[mt][j], ah[mt], bb.x, bb.y);    // Ahi*Bhi
                MMA(acc[mt][j], ah[mt], bb.z, bb.w);    // Ahi*Blo
                MMA(acc[mt][j], al[mt], bb.x, bb.y);    // Alo*Bhi
            }
            bb = bbn;
        }
    }
}

// ---------------- main kernel ----------------
__global__ void __launch_bounds__(512, 1) commnet_mma_kernel(
    const int*   __restrict__ ids,
    const float* __restrict__ b1,
    const float* __restrict__ b2,
    const float* __restrict__ Wd,
    const float* __restrict__ bd,
    const float* __restrict__ emb,
    float*       __restrict__ out)
{
    extern __shared__ uint8_t smraw[];
    uint32_t* sHi = reinterpret_cast<uint32_t*>(smraw);          // [128][72]
    uint32_t* sLo = sHi + 128 * SPITCH;
    float2*   G0s = reinterpret_cast<float2*>(sLo + 128 * SPITCH);
    float*    Sv  = reinterpret_cast<float*>(G0s + 128 * SPITCH);
    float*    Tv  = Sv + HID;

    const int cta  = blockIdx.x;
    const int tid  = threadIdx.x;
    const int w    = tid >> 5;
    const int lane = tid & 31;
    const int g    = lane >> 2;
    const int t    = lane & 3;

    // ---- gather: h0 -> split pairs in S ----
    {
        int r  = tid >> 3;
        int c8 = tid & 7;
        int aid = ids[cta * MAG + r];
        const float4* er = reinterpret_cast<const float4*>(emb + aid * HID) + c8 * 8;
        #pragma unroll
        for (int q = 0; q < 8; ++q) {
            float4 e = er[q];
            int pair = (c8 * 32 + q * 4) >> 1;
            uint32_t hi, lo;
            split2(e.x, e.y, hi, lo);
            sHi[pair * SPITCH + r] = hi; sLo[pair * SPITCH + r] = lo;
            split2(e.z, e.w, hi, lo);
            sHi[(pair + 1) * SPITCH + r] = hi; sLo[(pair + 1) * SPITCH + r] = lo;
        }
    }

    for (int step = 0; step < STEPS; ++step) {
        __syncthreads();

        // ---- Sv[k] = sum_m h[m][k] ----
        if (tid < HID) {
            int pair = tid >> 1, half = tid & 1;
            float s = 0.f;
            #pragma unroll 8
            for (int m = 0; m < MAG; ++m) {
                uint32_t hv = sHi[pair * SPITCH + m];
                uint32_t lv = sLo[pair * SPITCH + m];
                __nv_bfloat162 hb = *reinterpret_cast<__nv_bfloat162*>(&hv);
                __nv_bfloat162 lb = *reinterpret_cast<__nv_bfloat162*>(&lv);
                s += half ? (__bfloat162float(hb.y) + __bfloat162float(lb.y))
                          : (__bfloat162float(hb.x) + __bfloat162float(lb.x));
            }
            Sv[tid] = s;
        }
        __syncthreads();

        // ---- Tv[c] = b1[c] + inv * (Sv @ W1b)[c] ----
        for (int i = 0; i < 16; ++i) {
            int c = w * 16 + i;
            float p = 0.f;
            #pragma unroll
            for (int q = 0; q < 8; ++q) {
                int k = lane + 32 * q;
                p = fmaf(Sv[k], __ldg(&gW1bT[c * HID + k]), p);
            }
            #pragma unroll
            for (int off = 16; off; off >>= 1)
                p += __shfl_xor_sync(0xFFFFFFFFu, p, off);
            if (lane == 0) Tv[c] = fmaf(p, INVF, b1[c]);
        }

        // ---- GEMM1 ----
        float acc[4][2][4];
        if (step == 0) {
            #pragma unroll
            for (int mt = 0; mt < 4; ++mt)
                #pragma unroll
                for (int j = 0; j < 2; ++j)
                    #pragma unroll
                    for (int q = 0; q < 4; ++q) acc[mt][j][q] = 0.f;
            gemm_pass(gPk[1], acc, sHi, sLo, w, lane, g, t);   // G0 = h0 @ W1c
            #pragma unroll
            for (int mt = 0; mt < 4; ++mt)
                #pragma unroll
                for (int j = 0; j < 2; ++j) {
                    int pair = 8 * w + 4 * j + t, m0 = mt * 16 + g;
                    G0s[pair * SPITCH + m0]     = make_float2(acc[mt][j][0], acc[mt][j][1]);
                    G0s[pair * SPITCH + m0 + 8] = make_float2(acc[mt][j][2], acc[mt][j][3]);
                }
        } else {
            #pragma unroll
            for (int mt = 0; mt < 4; ++mt)
                #pragma unroll
                for (int j = 0; j < 2; ++j) {
                    int pair = 8 * w + 4 * j + t, m0 = mt * 16 + g;
                    float2 ga = G0s[pair * SPITCH + m0];
                    float2 gb = G0s[pair * SPITCH + m0 + 8];
                    acc[mt][j][0] = ga.x; acc[mt][j][1] = ga.y;
                    acc[mt][j][2] = gb.x; acc[mt][j][3] = gb.y;
                }
        }
        gemm_pass(gPk[0], acc, sHi, sLo, w, lane, g, t);       // += h @ W1eff
        __syncthreads();

        // ---- epilogue1: act = relu(acc+Tv) -> S ; acc = h_old + b2 ----
        #pragma unroll
        for (int mt = 0; mt < 4; ++mt)
            #pragma unroll
            for (int j = 0; j < 2; ++j) {
                int pair = 8 * w + 4 * j + t, m0 = mt * 16 + g;
                int n0 = 16 * w + 8 * j + 2 * t;
                float2 hoa = unsplit(sHi[pair * SPITCH + m0],     sLo[pair * SPITCH + m0]);
                float2 hob = unsplit(sHi[pair * SPITCH + m0 + 8], sLo[pair * SPITCH + m0 + 8]);
                float tv0 = Tv[n0], tv1 = Tv[n0 + 1];
                float a0 = fmaxf(acc[mt][j][0] + tv0, 0.f);
                float a1 = fmaxf(acc[mt][j][1] + tv1, 0.f);
                float a2 = fmaxf(acc[mt][j][2] + tv0, 0.f);
                float a3 = fmaxf(acc[mt][j][3] + tv1, 0.f);
                uint32_t hi, lo;
                split2(a0, a1, hi, lo);
                sHi[pair * SPITCH + m0] = hi;     sLo[pair * SPITCH + m0] = lo;
                split2(a2, a3, hi, lo);
                sHi[pair * SPITCH + m0 + 8] = hi; sLo[pair * SPITCH + m0 + 8] = lo;
                float bb0 = __ldg(&b2[n0]), bb1 = __ldg(&b2[n0 + 1]);
                acc[mt][j][0] = hoa.x + bb0; acc[mt][j][1] = hoa.y + bb1;
                acc[mt][j][2] = hob.x + bb0; acc[mt][j][3] = hob.y + bb1;
            }
        __syncthreads();

        // ---- GEMM2: acc += act @ W2  (acc = new h) ----
        gemm_pass(gPk[2], acc, sHi, sLo, w, lane, g, t);
        __syncthreads();

        // ---- epilogue2: split new h -> S ----
        #pragma unroll
        for (int mt = 0; mt < 4; ++mt)
            #pragma unroll
            for (int j = 0; j < 2; ++j) {
                int pair = 8 * w + 4 * j + t, m0 = mt * 16 + g;
                uint32_t hi, lo;
                split2(acc[mt][j][0], acc[mt][j][1], hi, lo);
                sHi[pair * SPITCH + m0] = hi;     sLo[pair * SPITCH + m0] = lo;
                split2(acc[mt][j][2], acc[mt][j][3], hi, lo);
                sHi[pair * SPITCH + m0 + 8] = hi; sLo[pair * SPITCH + m0 + 8] = lo;
            }
    }

    __syncthreads();
    // ---- logits ----
    {
        int m  = tid >> 3;
        int a0 = (tid & 7) * 2;
        float s0 = 0.f, s1 = 0.f;
        #pragma unroll 4
        for (int pair = 0; pair < 128; ++pair) {
            float2 hp = unsplit(sHi[pair * SPITCH + m], sLo[pair * SPITCH + m]);
            int k = pair * 2;
            float2 w0 = *reinterpret_cast<const float2*>(Wd + k * 16 + a0);
            float2 w1 = *reinterpret_cast<const float2*>(Wd + (k + 1) * 16 + a0);
            s0 = fmaf(hp.x, w0.x, s0); s1 = fmaf(hp.x, w0.y, s1);
            s0 = fmaf(hp.y, w1.x, s0); s1 = fmaf(hp.y, w1.y, s1);
        }
        float* op = out + (cta * MAG + m) * 16 + a0;
        op[0] = s0 + bd[a0];
        op[1] = s1 + bd[a0 + 1];
    }
}

extern "C" void kernel_launch(void* const* d_in, const int* in_sizes, int n_in,
                              void* d_out, int out_size)
{
    const int*   ids = (const int*)  d_in[0];
    const float* emb = (const float*)d_in[1];
    const float* W1  = (const float*)d_in[2];
    const float* b1  = (const float*)d_in[3];
    const float* W2  = (const float*)d_in[4];
    const float* b2  = (const float*)d_in[5];
    const float* Wd  = (const float*)d_in[6];
    const float* bd  = (const float*)d_in[7];
    float* out = (float*)d_out;

    const int B = in_sizes[0] / MAG;      // 1024

    prep_pack<<<192, 256>>>(W1, W2);
    prep_t<<<HID, HID>>>(W1);

    cudaFuncSetAttribute(commnet_mma_kernel,
                         cudaFuncAttributeMaxDynamicSharedMemorySize, SMEM_BYTES);
    commnet_mma_kernel<<<B, 512, SMEM_BYTES>>>(ids, b1, b2, Wd, bd, emb, out);
}